// round 1
// baseline (speedup 1.0000x reference)
#include <cuda_runtime.h>
#include <cstdint>

#define S_LEN   2048
#define BATCH   2
#define DIM     4096
#define NH      32
#define KVHEADS 8
#define HD      128
#define MROWS   (BATCH * S_LEN)     // 4096
#define KVDIM   (KVHEADS * HD)      // 1024

// Scratch (allocation-free rule: __device__ globals)
__device__ float g_q[(size_t)MROWS * DIM];     // 64 MB
__device__ float g_k[(size_t)MROWS * KVDIM];   // 16 MB
__device__ float g_v[(size_t)MROWS * KVDIM];   // 16 MB
__device__ float g_att[(size_t)MROWS * DIM];   // 64 MB

// ---------------------------------------------------------------------------
// C[M,N] = A[M,K] * B[N,K]^T   (both row-major; dot over contiguous K)
// 128x128 tile, BK=8, 256 threads, 8x8 micro-tile (interleaved 4+4 fragments
// so all shared-memory reads are bank-conflict-free).
// ---------------------------------------------------------------------------
__global__ __launch_bounds__(256, 2)
void sgemm_nt(const float* __restrict__ A, const float* __restrict__ B,
              float* __restrict__ C, int M, int N, int K)
{
    __shared__ float As[8][132];
    __shared__ float Bs[8][132];

    const int bm = blockIdx.y * 128;
    const int bn = blockIdx.x * 128;
    const int tid  = threadIdx.x;
    const int warp = tid >> 5;
    const int lane = tid & 31;
    const int warp_m = warp >> 2;      // 0..1  (64-row warp tile)
    const int warp_n = warp & 3;       // 0..3  (32-col warp tile)
    const int wm = lane >> 2;          // 0..7
    const int wn = lane & 3;           // 0..3

    // float4 indices into 128-wide tile rows
    const int mA = warp_m * 16 + wm;   // + 8  for second fragment
    const int nB = warp_n * 8  + wn;   // + 4  for second fragment

    const int lr = tid >> 1;           // 0..127 row within tile
    const int lc = (tid & 1) * 4;      // 0 or 4

    const float* Ab = A + (size_t)bm * K;
    const float* Bb = B + (size_t)bn * K;

    float acc[8][8];
#pragma unroll
    for (int i = 0; i < 8; i++)
#pragma unroll
        for (int j = 0; j < 8; j++) acc[i][j] = 0.f;

    for (int k0 = 0; k0 < K; k0 += 8) {
        float4 a = *(const float4*)(Ab + (size_t)lr * K + k0 + lc);
        float4 b = *(const float4*)(Bb + (size_t)lr * K + k0 + lc);
        As[lc + 0][lr] = a.x; As[lc + 1][lr] = a.y;
        As[lc + 2][lr] = a.z; As[lc + 3][lr] = a.w;
        Bs[lc + 0][lr] = b.x; Bs[lc + 1][lr] = b.y;
        Bs[lc + 2][lr] = b.z; Bs[lc + 3][lr] = b.w;
        __syncthreads();

#pragma unroll
        for (int k = 0; k < 8; k++) {
            const float4* Ar = (const float4*)&As[k][0];
            const float4* Br = (const float4*)&Bs[k][0];
            float4 a0 = Ar[mA];
            float4 a1 = Ar[mA + 8];
            float4 b0 = Br[nB];
            float4 b1 = Br[nB + 4];
            float rm[8] = {a0.x, a0.y, a0.z, a0.w, a1.x, a1.y, a1.z, a1.w};
            float rn[8] = {b0.x, b0.y, b0.z, b0.w, b1.x, b1.y, b1.z, b1.w};
#pragma unroll
            for (int i = 0; i < 8; i++)
#pragma unroll
                for (int j = 0; j < 8; j++)
                    acc[i][j] += rm[i] * rn[j];
        }
        __syncthreads();
    }

    // Store: rows warp_m*64 + {0,32} + wm*4 + i ; cols warp_n*32 + {0,16} + wn*4 + j
#pragma unroll
    for (int ii = 0; ii < 2; ii++) {
#pragma unroll
        for (int i = 0; i < 4; i++) {
            int row = bm + warp_m * 64 + ii * 32 + wm * 4 + i;
            float* crow = C + (size_t)row * N + bn + warp_n * 32;
            float4 c0 = make_float4(acc[ii*4+i][0], acc[ii*4+i][1],
                                    acc[ii*4+i][2], acc[ii*4+i][3]);
            float4 c1 = make_float4(acc[ii*4+i][4], acc[ii*4+i][5],
                                    acc[ii*4+i][6], acc[ii*4+i][7]);
            *(float4*)(crow + wn * 4)      = c0;
            *(float4*)(crow + 16 + wn * 4) = c1;
        }
    }
}

// ---------------------------------------------------------------------------
// RoPE on g_q [MROWS, DIM] and g_k [MROWS, KVDIM] in place.
// Pairs are interleaved (even, odd) within each head dim.
// ---------------------------------------------------------------------------
__global__ void rope_kernel(const float* __restrict__ cosp,
                            const float* __restrict__ sinp)
{
    int idx = blockIdx.x * blockDim.x + threadIdx.x;
    const int QP = MROWS * (DIM / 2);      // 8388608
    const int KP = MROWS * (KVDIM / 2);    // 2097152
    if (idx < QP) {
        int row = idx >> 11;               // / (DIM/2)
        int col = idx & 2047;
        int s = row & (S_LEN - 1);
        int i = col & 63;                  // pair index within head
        float c  = cosp[s * 64 + i];
        float sn = sinp[s * 64 + i];
        float2* p = (float2*)(g_q + (size_t)row * DIM) + col;
        float2 v = *p;
        *p = make_float2(v.x * c - v.y * sn, v.x * sn + v.y * c);
    } else if (idx < QP + KP) {
        int j = idx - QP;
        int row = j >> 9;                  // / (KVDIM/2)
        int col = j & 511;
        int s = row & (S_LEN - 1);
        int i = col & 63;
        float c  = cosp[s * 64 + i];
        float sn = sinp[s * 64 + i];
        float2* p = (float2*)(g_k + (size_t)row * KVDIM) + col;
        float2 v = *p;
        *p = make_float2(v.x * c - v.y * sn, v.x * sn + v.y * c);
    }
}

// ---------------------------------------------------------------------------
// Causal flash attention. One block per (b, h, 32-row q tile), 128 threads.
// Thread (r = tid>>2, quad = tid&3):
//   scores: columns c = quad + 4j (j=0..7)
//   output: columns j*16 + quad*4 .. +4 (j=0..7), full over all keys.
// K and V share one smem buffer (reloaded), keeping smem under 48 KB.
// ---------------------------------------------------------------------------
__global__ __launch_bounds__(128)
void attn_kernel()
{
    __shared__ float Qs[32][132];
    __shared__ float KVs[32][132];

    const int qb = blockIdx.x, h = blockIdx.y, b = blockIdx.z;
    const int kvh = h >> 2;                     // N_REP = 4
    const int tid = threadIdx.x;
    const int lane = tid & 31;
    const int r = tid >> 2;                     // q row within tile
    const int quad = tid & 3;
    const int q0 = qb * 32;

    const float* qptr = g_q + ((size_t)(b * S_LEN + q0)) * DIM + h * HD;
    for (int i = tid; i < 32 * 32; i += 128) {
        int rr = i >> 5, cc = i & 31;
        *(float4*)&Qs[rr][cc * 4] =
            *(const float4*)(qptr + (size_t)rr * DIM + cc * 4);
    }

    float m = -1e30f, l = 0.f;
    float acc[8][4];
#pragma unroll
    for (int j = 0; j < 8; j++)
#pragma unroll
        for (int d = 0; d < 4; d++) acc[j][d] = 0.f;

    const float scale = 0.08838834764831845f;   // 1/sqrt(128)
    const int ntiles = qb + 1;
    const float* kbase = g_k + ((size_t)(b * S_LEN)) * KVDIM + kvh * HD;
    const float* vbase = g_v + ((size_t)(b * S_LEN)) * KVDIM + kvh * HD;

    for (int t = 0; t < ntiles; t++) {
        const int k0 = t * 32;
        __syncthreads();
        for (int i = tid; i < 32 * 32; i += 128) {
            int rr = i >> 5, cc = i & 31;
            *(float4*)&KVs[rr][cc * 4] =
                *(const float4*)(kbase + (size_t)(k0 + rr) * KVDIM + cc * 4);
        }
        __syncthreads();

        // scores for columns c = quad + 4j
        float sc[8];
#pragma unroll
        for (int j = 0; j < 8; j++) sc[j] = 0.f;
#pragma unroll 4
        for (int d4 = 0; d4 < 32; d4++) {
            float4 qv = *(float4*)&Qs[r][d4 * 4];
#pragma unroll
            for (int j = 0; j < 8; j++) {
                float4 kv = *(float4*)&KVs[quad + j * 4][d4 * 4];
                sc[j] += qv.x * kv.x + qv.y * kv.y + qv.z * kv.z + qv.w * kv.w;
            }
        }

        const bool diag = (t == qb);
        float tmax = -1e30f;
#pragma unroll
        for (int j = 0; j < 8; j++) {
            int c = quad + j * 4;
            sc[j] *= scale;
            if (diag && c > r) sc[j] = -1e30f;
            tmax = fmaxf(tmax, sc[j]);
        }
        tmax = fmaxf(tmax, __shfl_xor_sync(0xffffffffu, tmax, 1));
        tmax = fmaxf(tmax, __shfl_xor_sync(0xffffffffu, tmax, 2));
        float m_new = fmaxf(m, tmax);
        float corr = __expf(m - m_new);
        m = m_new;
        l *= corr;
#pragma unroll
        for (int j = 0; j < 8; j++)
#pragma unroll
            for (int d = 0; d < 4; d++) acc[j][d] *= corr;

        float p[8];
#pragma unroll
        for (int j = 0; j < 8; j++) {
            p[j] = __expf(sc[j] - m_new);
            l += p[j];
        }

        __syncthreads();   // done reading K
        for (int i = tid; i < 32 * 32; i += 128) {
            int rr = i >> 5, cc = i & 31;
            *(float4*)&KVs[rr][cc * 4] =
                *(const float4*)(vbase + (size_t)(k0 + rr) * KVDIM + cc * 4);
        }
        __syncthreads();

#pragma unroll
        for (int c = 0; c < 32; c++) {
            float pv = __shfl_sync(0xffffffffu, p[c >> 2],
                                   (lane & ~3) | (c & 3));
#pragma unroll
            for (int j = 0; j < 8; j++) {
                float4 v = *(float4*)&KVs[c][(j * 4 + quad) * 4];
                acc[j][0] += pv * v.x;
                acc[j][1] += pv * v.y;
                acc[j][2] += pv * v.z;
                acc[j][3] += pv * v.w;
            }
        }
    }

    // row sum of l across the quad, then normalize + store
    l += __shfl_xor_sync(0xffffffffu, l, 1);
    l += __shfl_xor_sync(0xffffffffu, l, 2);
    float inv = 1.f / l;

    float* optr = g_att + ((size_t)(b * S_LEN + q0 + r)) * DIM + h * HD;
#pragma unroll
    for (int j = 0; j < 8; j++) {
        float4 o = make_float4(acc[j][0] * inv, acc[j][1] * inv,
                               acc[j][2] * inv, acc[j][3] * inv);
        *(float4*)(optr + j * 16 + quad * 4) = o;
    }
}

// ---------------------------------------------------------------------------
extern "C" void kernel_launch(void* const* d_in, const int* in_sizes, int n_in,
                              void* d_out, int out_size)
{
    (void)in_sizes; (void)n_in; (void)out_size;
    const float* x  = (const float*)d_in[0];
    const float* wq = (const float*)d_in[1];
    const float* wk = (const float*)d_in[2];
    const float* wv = (const float*)d_in[3];
    const float* wo = (const float*)d_in[4];
    const float* fc = (const float*)d_in[5];
    const float* fs = (const float*)d_in[6];
    // d_in[7] = mask (implicit causal), d_in[8] = start_pos (0)
    float* out = (float*)d_out;

    float *q, *k, *v, *att;
    cudaGetSymbolAddress((void**)&q,   g_q);
    cudaGetSymbolAddress((void**)&k,   g_k);
    cudaGetSymbolAddress((void**)&v,   g_v);
    cudaGetSymbolAddress((void**)&att, g_att);

    // QKV projections
    sgemm_nt<<<dim3(DIM / 128,   MROWS / 128), 256>>>(x, wq, q, MROWS, DIM,   DIM);
    sgemm_nt<<<dim3(KVDIM / 128, MROWS / 128), 256>>>(x, wk, k, MROWS, KVDIM, DIM);
    sgemm_nt<<<dim3(KVDIM / 128, MROWS / 128), 256>>>(x, wv, v, MROWS, KVDIM, DIM);

    // RoPE on Q and K
    const int total_pairs = MROWS * (DIM / 2) + MROWS * (KVDIM / 2);
    rope_kernel<<<(total_pairs + 255) / 256, 256>>>(fc, fs);

    // Causal GQA flash attention
    attn_kernel<<<dim3(S_LEN / 32, NH, BATCH), 128>>>();

    // Output projection
    sgemm_nt<<<dim3(DIM / 128, MROWS / 128), 256>>>(att, wo, out, MROWS, DIM, DIM);
}

// round 3
// speedup vs baseline: 1.6724x; 1.6724x over previous
#include <cuda_runtime.h>
#include <cuda_bf16.h>
#include <cstdint>

#define S_LEN   2048
#define BATCH   2
#define DIM     4096
#define NH      32
#define KVHEADS 8
#define HD      128
#define MROWS   (BATCH * S_LEN)     // 4096
#define KVDIM   (KVHEADS * HD)      // 1024
#define KDIM    4096                // inner dim for all 4 GEMMs

// ---------------- scratch (__device__ globals; allocation-free rule) -------
__device__ float g_q[(size_t)MROWS * DIM];
__device__ float g_k[(size_t)MROWS * KVDIM];
__device__ float g_v[(size_t)MROWS * KVDIM];
__device__ float g_att[(size_t)MROWS * DIM];

__device__ __nv_bfloat16 g_xhi[(size_t)MROWS * KDIM];
__device__ __nv_bfloat16 g_xlo[(size_t)MROWS * KDIM];
__device__ __nv_bfloat16 g_wqhi[(size_t)DIM * KDIM];
__device__ __nv_bfloat16 g_wqlo[(size_t)DIM * KDIM];
__device__ __nv_bfloat16 g_wkhi[(size_t)KVDIM * KDIM];
__device__ __nv_bfloat16 g_wklo[(size_t)KVDIM * KDIM];
__device__ __nv_bfloat16 g_wvhi[(size_t)KVDIM * KDIM];
__device__ __nv_bfloat16 g_wvlo[(size_t)KVDIM * KDIM];
__device__ __nv_bfloat16 g_wohi[(size_t)DIM * KDIM];
__device__ __nv_bfloat16 g_wolo[(size_t)DIM * KDIM];
__device__ __nv_bfloat16 g_ahi[(size_t)MROWS * DIM];
__device__ __nv_bfloat16 g_alo[(size_t)MROWS * DIM];

// ---------------- helpers ----------------------------------------------
__device__ __forceinline__ uint32_t smem_u32(const void* p) {
    uint32_t a;
    asm("{ .reg .u64 t; cvta.to.shared.u64 t, %1; cvt.u32.u64 %0, t; }"
        : "=r"(a) : "l"(p));
    return a;
}

__device__ __forceinline__ void ldsm4(uint32_t* d, uint32_t addr) {
    asm volatile("ldmatrix.sync.aligned.m8n8.x4.shared.b16 {%0,%1,%2,%3}, [%4];"
                 : "=r"(d[0]), "=r"(d[1]), "=r"(d[2]), "=r"(d[3]) : "r"(addr));
}

__device__ __forceinline__ void mma16816(float* c, const uint32_t* a,
                                         uint32_t b0, uint32_t b1) {
    asm volatile(
        "mma.sync.aligned.m16n8k16.row.col.f32.bf16.bf16.f32 "
        "{%0,%1,%2,%3}, {%4,%5,%6,%7}, {%8,%9}, {%0,%1,%2,%3};"
        : "+f"(c[0]), "+f"(c[1]), "+f"(c[2]), "+f"(c[3])
        : "r"(a[0]), "r"(a[1]), "r"(a[2]), "r"(a[3]), "r"(b0), "r"(b1));
}

#define CP_ASYNC16(dst, src) \
    asm volatile("cp.async.cg.shared.global [%0], [%1], 16;" \
                 :: "r"(dst), "l"(src) : "memory")
#define CP_COMMIT()  asm volatile("cp.async.commit_group;" ::: "memory")
#define CP_WAIT1()   asm volatile("cp.async.wait_group 1;" ::: "memory")

// ---------------------------------------------------------------------------
// fp32 -> (bf16 hi, bf16 lo) split
// ---------------------------------------------------------------------------
__global__ void split_kernel(const float* __restrict__ src,
                             __nv_bfloat16* __restrict__ hi,
                             __nv_bfloat16* __restrict__ lo, int n)
{
    int i = blockIdx.x * blockDim.x + threadIdx.x;
    if (i < n) {
        float f = src[i];
        __nv_bfloat16 h = __float2bfloat16(f);
        hi[i] = h;
        lo[i] = __float2bfloat16(f - __bfloat162float(h));
    }
}

// ---------------------------------------------------------------------------
// HMMA GEMM: C[M,N] = A[M,K] * B[N,K]^T  via bf16x3 split (hi*hi+hi*lo+lo*hi).
// 128x128x32 block tile, 8 warps (2x4), 64x32 warp tile, m16n8k16 MMAs,
// cp.async double-buffered smem with 40-elem padded rows (conflict-free
// ldmatrix).
// ---------------------------------------------------------------------------
#define BM 128
#define BN 128
#define BK 32
#define PADC 40
#define SPLIT_BYTES (BM * PADC * 2)        // 10240 per split tile
#define STAGE_BYTES (4 * SPLIT_BYTES)      // Ah, Al, Bh, Bl = 40960
#define GEMM_SMEM   (2 * STAGE_BYTES)      // 81920

__global__ void __launch_bounds__(256)
gemm_mma(const __nv_bfloat16* __restrict__ Ahi,
         const __nv_bfloat16* __restrict__ Alo,
         const __nv_bfloat16* __restrict__ Bhi,
         const __nv_bfloat16* __restrict__ Blo,
         float* __restrict__ C, int N)
{
    extern __shared__ char smem[];
    const int K = KDIM;
    const uint32_t sbase = smem_u32(smem);
    const int tid = threadIdx.x;
    const int wid = tid >> 5;
    const int lane = tid & 31;
    const int warp_m = wid >> 2;       // 0..1 : 64-row warp tile
    const int warp_n = wid & 3;        // 0..3 : 32-col warp tile
    const int bm = blockIdx.y * BM;
    const int bn = blockIdx.x * BN;
    const int NCH = K / BK;            // 128

    float acc[4][4][4];
#pragma unroll
    for (int i = 0; i < 4; i++)
#pragma unroll
        for (int j = 0; j < 4; j++)
#pragma unroll
            for (int r = 0; r < 4; r++) acc[i][j][r] = 0.f;

    // per-lane ldmatrix offsets (within a split tile, in elements)
    const int a_row = lane & 15;             // + mt*16 + warp_m*64
    const int a_col = (lane >> 4) * 8;       // + ks*16
    const int b_row = ((lane >> 4) * 8) + (lane & 7);   // + np*16 + warp_n*32
    const int b_col = ((lane >> 3) & 1) * 8;            // + ks*16

    // ---- async stage loader ------------------------------------------------
    auto load_stage = [&](int ch, int st) {
        if (ch < NCH) {
            const int kc = ch * BK;
            const uint32_t base = sbase + st * STAGE_BYTES;
#pragma unroll
            for (int i = 0; i < 8; i++) {
                int u = tid + i * 256;          // 0..2047
                int isB   = u >> 10;
                int v     = u & 1023;
                int split = v >> 9;
                int idx   = v & 511;
                int row   = idx >> 2;
                int ck    = (idx & 3) * 8;
                const __nv_bfloat16* src;
                if (!isB) src = (split ? Alo : Ahi) + (size_t)(bm + row) * K + kc + ck;
                else      src = (split ? Blo : Bhi) + (size_t)(bn + row) * K + kc + ck;
                uint32_t dst = base + (uint32_t)((isB * 2 + split) * SPLIT_BYTES)
                             + (uint32_t)(row * PADC + ck) * 2;
                CP_ASYNC16(dst, src);
            }
        }
        CP_COMMIT();
    };

    load_stage(0, 0);
    load_stage(1, 1);

    for (int ch = 0; ch < NCH; ch++) {
        const int st = ch & 1;
        CP_WAIT1();
        __syncthreads();

        const uint32_t tb = sbase + st * STAGE_BYTES;
#pragma unroll
        for (int ks = 0; ks < 2; ks++) {
            // A fragments: hi and lo, 4 m-tiles each
            uint32_t afr[2][4][4];
#pragma unroll
            for (int s = 0; s < 2; s++) {
#pragma unroll
                for (int mt = 0; mt < 4; mt++) {
                    uint32_t addr = tb + s * SPLIT_BYTES
                        + (uint32_t)((warp_m * 64 + mt * 16 + a_row) * PADC
                                     + ks * 16 + a_col) * 2;
                    ldsm4(afr[s][mt], addr);
                }
            }
            // B fragments: hi and lo, 2 n-pairs (4 n-tiles) each
            uint32_t bfr[2][2][4];
#pragma unroll
            for (int s = 0; s < 2; s++) {
#pragma unroll
                for (int np = 0; np < 2; np++) {
                    uint32_t addr = tb + (2 + s) * SPLIT_BYTES
                        + (uint32_t)((warp_n * 32 + np * 16 + b_row) * PADC
                                     + ks * 16 + b_col) * 2;
                    ldsm4(bfr[s][np], addr);
                }
            }
#pragma unroll
            for (int mt = 0; mt < 4; mt++) {
#pragma unroll
                for (int nt = 0; nt < 4; nt++) {
                    uint32_t bh0 = bfr[0][nt >> 1][(nt & 1) * 2];
                    uint32_t bh1 = bfr[0][nt >> 1][(nt & 1) * 2 + 1];
                    uint32_t bl0 = bfr[1][nt >> 1][(nt & 1) * 2];
                    uint32_t bl1 = bfr[1][nt >> 1][(nt & 1) * 2 + 1];
                    mma16816(acc[mt][nt], afr[0][mt], bh0, bh1);  // hi*hi
                    mma16816(acc[mt][nt], afr[0][mt], bl0, bl1);  // hi*lo
                    mma16816(acc[mt][nt], afr[1][mt], bh0, bh1);  // lo*hi
                }
            }
        }
        __syncthreads();
        load_stage(ch + 2, st);
    }

    // ---- epilogue ----------------------------------------------------------
#pragma unroll
    for (int mt = 0; mt < 4; mt++) {
#pragma unroll
        for (int nt = 0; nt < 4; nt++) {
            int row0 = bm + warp_m * 64 + mt * 16 + (lane >> 2);
            int col  = bn + warp_n * 32 + nt * 8 + (lane & 3) * 2;
            float2 v0 = make_float2(acc[mt][nt][0], acc[mt][nt][1]);
            float2 v1 = make_float2(acc[mt][nt][2], acc[mt][nt][3]);
            *(float2*)(C + (size_t)row0 * N + col)       = v0;
            *(float2*)(C + (size_t)(row0 + 8) * N + col) = v1;
        }
    }
}

// ---------------------------------------------------------------------------
// RoPE on g_q [MROWS, DIM] and g_k [MROWS, KVDIM] in place.
// ---------------------------------------------------------------------------
__global__ void rope_kernel(const float* __restrict__ cosp,
                            const float* __restrict__ sinp)
{
    int idx = blockIdx.x * blockDim.x + threadIdx.x;
    const int QP = MROWS * (DIM / 2);
    const int KP = MROWS * (KVDIM / 2);
    if (idx < QP) {
        int row = idx >> 11;
        int col = idx & 2047;
        int s = row & (S_LEN - 1);
        int i = col & 63;
        float c  = cosp[s * 64 + i];
        float sn = sinp[s * 64 + i];
        float2* p = (float2*)(g_q + (size_t)row * DIM) + col;
        float2 v = *p;
        *p = make_float2(v.x * c - v.y * sn, v.x * sn + v.y * c);
    } else if (idx < QP + KP) {
        int j = idx - QP;
        int row = j >> 9;
        int col = j & 511;
        int s = row & (S_LEN - 1);
        int i = col & 63;
        float c  = cosp[s * 64 + i];
        float sn = sinp[s * 64 + i];
        float2* p = (float2*)(g_k + (size_t)row * KVDIM) + col;
        float2 v = *p;
        *p = make_float2(v.x * c - v.y * sn, v.x * sn + v.y * c);
    }
}

// ---------------------------------------------------------------------------
// Causal flash attention (unchanged).
// ---------------------------------------------------------------------------
__global__ __launch_bounds__(128)
void attn_kernel()
{
    __shared__ float Qs[32][132];
    __shared__ float KVs[32][132];

    const int qb = blockIdx.x, h = blockIdx.y, b = blockIdx.z;
    const int kvh = h >> 2;
    const int tid = threadIdx.x;
    const int lane = tid & 31;
    const int r = tid >> 2;
    const int quad = tid & 3;
    const int q0 = qb * 32;

    const float* qptr = g_q + ((size_t)(b * S_LEN + q0)) * DIM + h * HD;
    for (int i = tid; i < 32 * 32; i += 128) {
        int rr = i >> 5, cc = i & 31;
        *(float4*)&Qs[rr][cc * 4] =
            *(const float4*)(qptr + (size_t)rr * DIM + cc * 4);
    }

    float m = -1e30f, l = 0.f;
    float acc[8][4];
#pragma unroll
    for (int j = 0; j < 8; j++)
#pragma unroll
        for (int d = 0; d < 4; d++) acc[j][d] = 0.f;

    const float scale = 0.08838834764831845f;
    const int ntiles = qb + 1;
    const float* kbase = g_k + ((size_t)(b * S_LEN)) * KVDIM + kvh * HD;
    const float* vbase = g_v + ((size_t)(b * S_LEN)) * KVDIM + kvh * HD;

    for (int t = 0; t < ntiles; t++) {
        const int k0 = t * 32;
        __syncthreads();
        for (int i = tid; i < 32 * 32; i += 128) {
            int rr = i >> 5, cc = i & 31;
            *(float4*)&KVs[rr][cc * 4] =
                *(const float4*)(kbase + (size_t)(k0 + rr) * KVDIM + cc * 4);
        }
        __syncthreads();

        float sc[8];
#pragma unroll
        for (int j = 0; j < 8; j++) sc[j] = 0.f;
#pragma unroll 4
        for (int d4 = 0; d4 < 32; d4++) {
            float4 qv = *(float4*)&Qs[r][d4 * 4];
#pragma unroll
            for (int j = 0; j < 8; j++) {
                float4 kv = *(float4*)&KVs[quad + j * 4][d4 * 4];
                sc[j] += qv.x * kv.x + qv.y * kv.y + qv.z * kv.z + qv.w * kv.w;
            }
        }

        const bool diag = (t == qb);
        float tmax = -1e30f;
#pragma unroll
        for (int j = 0; j < 8; j++) {
            int c = quad + j * 4;
            sc[j] *= scale;
            if (diag && c > r) sc[j] = -1e30f;
            tmax = fmaxf(tmax, sc[j]);
        }
        tmax = fmaxf(tmax, __shfl_xor_sync(0xffffffffu, tmax, 1));
        tmax = fmaxf(tmax, __shfl_xor_sync(0xffffffffu, tmax, 2));
        float m_new = fmaxf(m, tmax);
        float corr = __expf(m - m_new);
        m = m_new;
        l *= corr;
#pragma unroll
        for (int j = 0; j < 8; j++)
#pragma unroll
            for (int d = 0; d < 4; d++) acc[j][d] *= corr;

        float p[8];
#pragma unroll
        for (int j = 0; j < 8; j++) {
            p[j] = __expf(sc[j] - m_new);
            l += p[j];
        }

        __syncthreads();
        for (int i = tid; i < 32 * 32; i += 128) {
            int rr = i >> 5, cc = i & 31;
            *(float4*)&KVs[rr][cc * 4] =
                *(const float4*)(vbase + (size_t)(k0 + rr) * KVDIM + cc * 4);
        }
        __syncthreads();

#pragma unroll
        for (int c = 0; c < 32; c++) {
            float pv = __shfl_sync(0xffffffffu, p[c >> 2],
                                   (lane & ~3) | (c & 3));
#pragma unroll
            for (int j = 0; j < 8; j++) {
                float4 v = *(float4*)&KVs[c][(j * 4 + quad) * 4];
                acc[j][0] += pv * v.x;
                acc[j][1] += pv * v.y;
                acc[j][2] += pv * v.z;
                acc[j][3] += pv * v.w;
            }
        }
    }

    l += __shfl_xor_sync(0xffffffffu, l, 1);
    l += __shfl_xor_sync(0xffffffffu, l, 2);
    float inv = 1.f / l;

    float* optr = g_att + ((size_t)(b * S_LEN + q0 + r)) * DIM + h * HD;
#pragma unroll
    for (int j = 0; j < 8; j++) {
        float4 o = make_float4(acc[j][0] * inv, acc[j][1] * inv,
                               acc[j][2] * inv, acc[j][3] * inv);
        *(float4*)(optr + j * 16 + quad * 4) = o;
    }
}

// ---------------------------------------------------------------------------
extern "C" void kernel_launch(void* const* d_in, const int* in_sizes, int n_in,
                              void* d_out, int out_size)
{
    (void)in_sizes; (void)n_in; (void)out_size;
    const float* x  = (const float*)d_in[0];
    const float* wq = (const float*)d_in[1];
    const float* wk = (const float*)d_in[2];
    const float* wv = (const float*)d_in[3];
    const float* wo = (const float*)d_in[4];
    const float* fc = (const float*)d_in[5];
    const float* fs = (const float*)d_in[6];
    float* out = (float*)d_out;

    float *q, *k, *v, *att;
    cudaGetSymbolAddress((void**)&q,   g_q);
    cudaGetSymbolAddress((void**)&k,   g_k);
    cudaGetSymbolAddress((void**)&v,   g_v);
    cudaGetSymbolAddress((void**)&att, g_att);

    __nv_bfloat16 *xhi, *xlo, *wqhi, *wqlo, *wkhi, *wklo, *wvhi, *wvlo,
                  *wohi, *wolo, *ahi, *alo;
    cudaGetSymbolAddress((void**)&xhi,  g_xhi);
    cudaGetSymbolAddress((void**)&xlo,  g_xlo);
    cudaGetSymbolAddress((void**)&wqhi, g_wqhi);
    cudaGetSymbolAddress((void**)&wqlo, g_wqlo);
    cudaGetSymbolAddress((void**)&wkhi, g_wkhi);
    cudaGetSymbolAddress((void**)&wklo, g_wklo);
    cudaGetSymbolAddress((void**)&wvhi, g_wvhi);
    cudaGetSymbolAddress((void**)&wvlo, g_wvlo);
    cudaGetSymbolAddress((void**)&wohi, g_wohi);
    cudaGetSymbolAddress((void**)&wolo, g_wolo);
    cudaGetSymbolAddress((void**)&ahi,  g_ahi);
    cudaGetSymbolAddress((void**)&alo,  g_alo);

    cudaFuncSetAttribute(gemm_mma,
                         cudaFuncAttributeMaxDynamicSharedMemorySize,
                         GEMM_SMEM);

    const int NBIG = MROWS * KDIM;
    const int NKV  = KVDIM * KDIM;
    split_kernel<<<(NBIG + 255) / 256, 256>>>(x,  xhi,  xlo,  NBIG);
    split_kernel<<<(NBIG + 255) / 256, 256>>>(wq, wqhi, wqlo, NBIG);
    split_kernel<<<(NKV  + 255) / 256, 256>>>(wk, wkhi, wklo, NKV);
    split_kernel<<<(NKV  + 255) / 256, 256>>>(wv, wvhi, wvlo, NKV);
    split_kernel<<<(NBIG + 255) / 256, 256>>>(wo, wohi, wolo, NBIG);

    // QKV projections (tensor cores via mma.sync)
    gemm_mma<<<dim3(DIM / BN,   MROWS / BM), 256, GEMM_SMEM>>>(
        xhi, xlo, wqhi, wqlo, q, DIM);
    gemm_mma<<<dim3(KVDIM / BN, MROWS / BM), 256, GEMM_SMEM>>>(
        xhi, xlo, wkhi, wklo, k, KVDIM);
    gemm_mma<<<dim3(KVDIM / BN, MROWS / BM), 256, GEMM_SMEM>>>(
        xhi, xlo, wvhi, wvlo, v, KVDIM);

    // RoPE
    const int total_pairs = MROWS * (DIM / 2) + MROWS * (KVDIM / 2);
    rope_kernel<<<(total_pairs + 255) / 256, 256>>>(fc, fs);

    // Attention
    attn_kernel<<<dim3(S_LEN / 32, NH, BATCH), 128>>>();

    // O projection
    split_kernel<<<(NBIG + 255) / 256, 256>>>(att, ahi, alo, NBIG);
    gemm_mma<<<dim3(DIM / BN, MROWS / BM), 256, GEMM_SMEM>>>(
        ahi, alo, wohi, wolo, out, DIM);
}

// round 4
// speedup vs baseline: 3.3971x; 2.0312x over previous
#include <cuda_runtime.h>
#include <cuda_bf16.h>
#include <cstdint>

#define S_LEN   2048
#define BATCH   2
#define DIM     4096
#define NH      32
#define KVHEADS 8
#define HD      128
#define MROWS   (BATCH * S_LEN)     // 4096
#define KVDIM   (KVHEADS * HD)      // 1024
#define KDIM    4096

// ---------------- scratch (__device__ globals) ------------------------------
__device__ float g_q[(size_t)MROWS * DIM];
__device__ float g_k[(size_t)MROWS * KVDIM];
__device__ float g_v[(size_t)MROWS * KVDIM];

__device__ __nv_bfloat16 g_xhi[(size_t)MROWS * KDIM];
__device__ __nv_bfloat16 g_xlo[(size_t)MROWS * KDIM];
__device__ __nv_bfloat16 g_wqhi[(size_t)DIM * KDIM];
__device__ __nv_bfloat16 g_wqlo[(size_t)DIM * KDIM];
__device__ __nv_bfloat16 g_wkhi[(size_t)KVDIM * KDIM];
__device__ __nv_bfloat16 g_wklo[(size_t)KVDIM * KDIM];
__device__ __nv_bfloat16 g_wvhi[(size_t)KVDIM * KDIM];
__device__ __nv_bfloat16 g_wvlo[(size_t)KVDIM * KDIM];
__device__ __nv_bfloat16 g_wohi[(size_t)DIM * KDIM];
__device__ __nv_bfloat16 g_wolo[(size_t)DIM * KDIM];
__device__ __nv_bfloat16 g_ahi[(size_t)MROWS * DIM];
__device__ __nv_bfloat16 g_alo[(size_t)MROWS * DIM];
// post-rope bf16 splits for attention
__device__ __nv_bfloat16 g_qhi[(size_t)MROWS * DIM];
__device__ __nv_bfloat16 g_qlo[(size_t)MROWS * DIM];
__device__ __nv_bfloat16 g_khi[(size_t)MROWS * KVDIM];
__device__ __nv_bfloat16 g_klo[(size_t)MROWS * KVDIM];
__device__ __nv_bfloat16 g_vhi[(size_t)MROWS * KVDIM];
__device__ __nv_bfloat16 g_vlo[(size_t)MROWS * KVDIM];

// ---------------- helpers ----------------------------------------------
__device__ __forceinline__ uint32_t smem_u32(const void* p) {
    uint32_t a;
    asm("{ .reg .u64 t; cvta.to.shared.u64 t, %1; cvt.u32.u64 %0, t; }"
        : "=r"(a) : "l"(p));
    return a;
}
__device__ __forceinline__ void ldsm4(uint32_t* d, uint32_t addr) {
    asm volatile("ldmatrix.sync.aligned.m8n8.x4.shared.b16 {%0,%1,%2,%3}, [%4];"
                 : "=r"(d[0]), "=r"(d[1]), "=r"(d[2]), "=r"(d[3]) : "r"(addr));
}
__device__ __forceinline__ void ldsm4t(uint32_t* d, uint32_t addr) {
    asm volatile("ldmatrix.sync.aligned.m8n8.x4.trans.shared.b16 {%0,%1,%2,%3}, [%4];"
                 : "=r"(d[0]), "=r"(d[1]), "=r"(d[2]), "=r"(d[3]) : "r"(addr));
}
__device__ __forceinline__ void mma16816(float* c, const uint32_t* a,
                                         uint32_t b0, uint32_t b1) {
    asm volatile(
        "mma.sync.aligned.m16n8k16.row.col.f32.bf16.bf16.f32 "
        "{%0,%1,%2,%3}, {%4,%5,%6,%7}, {%8,%9}, {%0,%1,%2,%3};"
        : "+f"(c[0]), "+f"(c[1]), "+f"(c[2]), "+f"(c[3])
        : "r"(a[0]), "r"(a[1]), "r"(a[2]), "r"(a[3]), "r"(b0), "r"(b1));
}
#define CP_ASYNC16(dst, src) \
    asm volatile("cp.async.cg.shared.global [%0], [%1], 16;" \
                 :: "r"(dst), "l"(src) : "memory")
#define CP_COMMIT()  asm volatile("cp.async.commit_group;" ::: "memory")
#define CP_WAIT1()   asm volatile("cp.async.wait_group 1;" ::: "memory")

// ---------------------------------------------------------------------------
// fp32 -> (bf16 hi, bf16 lo) split
// ---------------------------------------------------------------------------
__global__ void split_kernel(const float* __restrict__ src,
                             __nv_bfloat16* __restrict__ hi,
                             __nv_bfloat16* __restrict__ lo, int n)
{
    int i = blockIdx.x * blockDim.x + threadIdx.x;
    if (i < n) {
        float f = src[i];
        __nv_bfloat16 h = __float2bfloat16(f);
        hi[i] = h;
        lo[i] = __float2bfloat16(f - __bfloat162float(h));
    }
}

// ---------------------------------------------------------------------------
// GEMM (unchanged from round 3): C = A * B^T via bf16x3 split, mma.sync.
// ---------------------------------------------------------------------------
#define BM 128
#define BN 128
#define BK 32
#define PADC 40
#define SPLIT_BYTES (BM * PADC * 2)
#define STAGE_BYTES (4 * SPLIT_BYTES)
#define GEMM_SMEM   (2 * STAGE_BYTES)

__global__ void __launch_bounds__(256)
gemm_mma(const __nv_bfloat16* __restrict__ Ahi,
         const __nv_bfloat16* __restrict__ Alo,
         const __nv_bfloat16* __restrict__ Bhi,
         const __nv_bfloat16* __restrict__ Blo,
         float* __restrict__ C, int N)
{
    extern __shared__ char smem[];
    const int K = KDIM;
    const uint32_t sbase = smem_u32(smem);
    const int tid = threadIdx.x;
    const int wid = tid >> 5;
    const int lane = tid & 31;
    const int warp_m = wid >> 2;
    const int warp_n = wid & 3;
    const int bm = blockIdx.y * BM;
    const int bn = blockIdx.x * BN;
    const int NCH = K / BK;

    float acc[4][4][4];
#pragma unroll
    for (int i = 0; i < 4; i++)
#pragma unroll
        for (int j = 0; j < 4; j++)
#pragma unroll
            for (int r = 0; r < 4; r++) acc[i][j][r] = 0.f;

    const int a_row = lane & 15;
    const int a_col = (lane >> 4) * 8;
    const int b_row = ((lane >> 4) * 8) + (lane & 7);
    const int b_col = ((lane >> 3) & 1) * 8;

    auto load_stage = [&](int ch, int st) {
        if (ch < NCH) {
            const int kc = ch * BK;
            const uint32_t base = sbase + st * STAGE_BYTES;
#pragma unroll
            for (int i = 0; i < 8; i++) {
                int u = tid + i * 256;
                int isB   = u >> 10;
                int v     = u & 1023;
                int split = v >> 9;
                int idx   = v & 511;
                int row   = idx >> 2;
                int ck    = (idx & 3) * 8;
                const __nv_bfloat16* src;
                if (!isB) src = (split ? Alo : Ahi) + (size_t)(bm + row) * K + kc + ck;
                else      src = (split ? Blo : Bhi) + (size_t)(bn + row) * K + kc + ck;
                uint32_t dst = base + (uint32_t)((isB * 2 + split) * SPLIT_BYTES)
                             + (uint32_t)(row * PADC + ck) * 2;
                CP_ASYNC16(dst, src);
            }
        }
        CP_COMMIT();
    };

    load_stage(0, 0);
    load_stage(1, 1);

    for (int ch = 0; ch < NCH; ch++) {
        const int st = ch & 1;
        CP_WAIT1();
        __syncthreads();
        const uint32_t tb = sbase + st * STAGE_BYTES;
#pragma unroll
        for (int ks = 0; ks < 2; ks++) {
            uint32_t afr[2][4][4];
#pragma unroll
            for (int s = 0; s < 2; s++)
#pragma unroll
                for (int mt = 0; mt < 4; mt++) {
                    uint32_t addr = tb + s * SPLIT_BYTES
                        + (uint32_t)((warp_m * 64 + mt * 16 + a_row) * PADC
                                     + ks * 16 + a_col) * 2;
                    ldsm4(afr[s][mt], addr);
                }
            uint32_t bfr[2][2][4];
#pragma unroll
            for (int s = 0; s < 2; s++)
#pragma unroll
                for (int np = 0; np < 2; np++) {
                    uint32_t addr = tb + (2 + s) * SPLIT_BYTES
                        + (uint32_t)((warp_n * 32 + np * 16 + b_row) * PADC
                                     + ks * 16 + b_col) * 2;
                    ldsm4(bfr[s][np], addr);
                }
#pragma unroll
            for (int mt = 0; mt < 4; mt++)
#pragma unroll
                for (int nt = 0; nt < 4; nt++) {
                    uint32_t bh0 = bfr[0][nt >> 1][(nt & 1) * 2];
                    uint32_t bh1 = bfr[0][nt >> 1][(nt & 1) * 2 + 1];
                    uint32_t bl0 = bfr[1][nt >> 1][(nt & 1) * 2];
                    uint32_t bl1 = bfr[1][nt >> 1][(nt & 1) * 2 + 1];
                    mma16816(acc[mt][nt], afr[0][mt], bh0, bh1);
                    mma16816(acc[mt][nt], afr[0][mt], bl0, bl1);
                    mma16816(acc[mt][nt], afr[1][mt], bh0, bh1);
                }
        }
        __syncthreads();
        load_stage(ch + 2, st);
    }

#pragma unroll
    for (int mt = 0; mt < 4; mt++)
#pragma unroll
        for (int nt = 0; nt < 4; nt++) {
            int row0 = bm + warp_m * 64 + mt * 16 + (lane >> 2);
            int col  = bn + warp_n * 32 + nt * 8 + (lane & 3) * 2;
            *(float2*)(C + (size_t)row0 * N + col) =
                make_float2(acc[mt][nt][0], acc[mt][nt][1]);
            *(float2*)(C + (size_t)(row0 + 8) * N + col) =
                make_float2(acc[mt][nt][2], acc[mt][nt][3]);
        }
}

// ---------------------------------------------------------------------------
// RoPE + bf16 hi/lo split: g_q -> (g_qhi, g_qlo), g_k -> (g_khi, g_klo)
// ---------------------------------------------------------------------------
__global__ void rope_split_kernel(const float* __restrict__ cosp,
                                  const float* __restrict__ sinp)
{
    int idx = blockIdx.x * blockDim.x + threadIdx.x;
    const int QP = MROWS * (DIM / 2);
    const int KP = MROWS * (KVDIM / 2);
    float2 v; float c, sn;
    __nv_bfloat16 *hi, *lo; size_t off;
    if (idx < QP) {
        int row = idx >> 11, col = idx & 2047;
        int s = row & (S_LEN - 1), i = col & 63;
        c = cosp[s * 64 + i]; sn = sinp[s * 64 + i];
        v = *((const float2*)(g_q + (size_t)row * DIM) + col);
        off = (size_t)row * DIM + 2 * col;
        hi = g_qhi; lo = g_qlo;
    } else if (idx < QP + KP) {
        int j = idx - QP;
        int row = j >> 9, col = j & 511;
        int s = row & (S_LEN - 1), i = col & 63;
        c = cosp[s * 64 + i]; sn = sinp[s * 64 + i];
        v = *((const float2*)(g_k + (size_t)row * KVDIM) + col);
        off = (size_t)row * KVDIM + 2 * col;
        hi = g_khi; lo = g_klo;
    } else return;
    float rx = v.x * c - v.y * sn;
    float ry = v.x * sn + v.y * c;
    __nv_bfloat162 h = __floats2bfloat162_rn(rx, ry);
    float lx = rx - __bfloat162float(h.x);
    float ly = ry - __bfloat162float(h.y);
    __nv_bfloat162 l = __floats2bfloat162_rn(lx, ly);
    *(__nv_bfloat162*)(hi + off) = h;
    *(__nv_bfloat162*)(lo + off) = l;
}

// ---------------------------------------------------------------------------
// Tensor-core causal flash attention.
// Block: 128 q rows, 8 warps (16 rows each). K/V tiles of 64 keys,
// cp.async double-buffered. bf16x3 for both S and PV GEMMs. Writes ahi/alo.
// ---------------------------------------------------------------------------
#define APAD   136
#define QSP    (128 * APAD * 2)       // 34816 per Q split
#define QBYTES (2 * QSP)              // 69632
#define KVSP   (64 * APAD * 2)        // 17408 per KV split
#define ASTAGE (4 * KVSP)             // 69632
#define ATTN_SMEM (QBYTES + 2 * ASTAGE)   // 208896

__global__ void __launch_bounds__(256)
attn_mma()
{
    extern __shared__ char smem[];
    const uint32_t sbase = smem_u32(smem);
    const int tid = threadIdx.x;
    const int warp = tid >> 5;
    const int lane = tid & 31;
    const int qb = blockIdx.x;
    const int h  = blockIdx.y;
    const int b  = blockIdx.z;
    const int kvh = h >> 2;
    const int q0 = qb * 128;
    const int bs = b * S_LEN;
    const int ntiles = 2 * qb + 2;

    const __nv_bfloat16* khi_b = g_khi + (size_t)bs * KVDIM + kvh * HD;
    const __nv_bfloat16* klo_b = g_klo + (size_t)bs * KVDIM + kvh * HD;
    const __nv_bfloat16* vhi_b = g_vhi + (size_t)bs * KVDIM + kvh * HD;
    const __nv_bfloat16* vlo_b = g_vlo + (size_t)bs * KVDIM + kvh * HD;

    // ---- Q load (async, joins group 0) -------------------------------------
    {
        const __nv_bfloat16* qhi_b = g_qhi + (size_t)(bs + q0) * DIM + h * HD;
        const __nv_bfloat16* qlo_b = g_qlo + (size_t)(bs + q0) * DIM + h * HD;
#pragma unroll
        for (int i = 0; i < 16; i++) {
            int u = tid + i * 256;           // 0..4095
            int split = u >> 11;
            int idx = u & 2047;
            int row = idx >> 4, ck = idx & 15;
            const __nv_bfloat16* src = (split ? qlo_b : qhi_b)
                                     + (size_t)row * DIM + ck * 8;
            uint32_t dst = sbase + split * QSP + (uint32_t)(row * APAD + ck * 8) * 2;
            CP_ASYNC16(dst, src);
        }
    }

    auto load_kv = [&](int t, int st) {
        if (t < ntiles) {
            const int k0 = t * 64;
            const uint32_t base = sbase + QBYTES + st * ASTAGE;
            const __nv_bfloat16* srcs[4] = {khi_b, klo_b, vhi_b, vlo_b};
#pragma unroll
            for (int i = 0; i < 16; i++) {
                int u = tid + i * 256;       // 0..4095
                int split = u >> 10;
                int idx = u & 1023;
                int row = idx >> 4, ck = idx & 15;
                const __nv_bfloat16* src = srcs[split]
                                         + (size_t)(k0 + row) * KVDIM + ck * 8;
                uint32_t dst = base + split * KVSP
                             + (uint32_t)(row * APAD + ck * 8) * 2;
                CP_ASYNC16(dst, src);
            }
        }
        CP_COMMIT();
    };

    load_kv(0, 0);
    load_kv(1, 1);

    // per-lane geometry
    const int r0 = lane >> 2;
    const int grow0 = q0 + warp * 16 + r0;
    const int grow1 = grow0 + 8;
    const int wmaxrow = q0 + warp * 16 + 15;
    const float scale = 0.08838834764831845f;

    float m0 = -1e30f, m1 = -1e30f, l0 = 0.f, l1 = 0.f;
    float oacc[16][4];
#pragma unroll
    for (int i = 0; i < 16; i++)
#pragma unroll
        for (int j = 0; j < 4; j++) oacc[i][j] = 0.f;

    const int qa_off = (warp * 16 + (lane & 15)) * APAD + (lane >> 4) * 8;
    const int kb_row = ((lane >> 4) * 8) + (lane & 7);
    const int kb_colh = ((lane >> 3) & 1) * 8;
    const int v_key = (lane & 7) + ((lane >> 3) & 1) * 8;
    const int v_hd  = (lane >> 4) * 8;

    for (int t = 0; t < ntiles; t++) {
        CP_WAIT1();
        __syncthreads();
        const int k0 = t * 64;
        const uint32_t kb = sbase + QBYTES + (t & 1) * ASTAGE;

        if (k0 <= wmaxrow) {
            // ---- S = Q K^T (bf16x3) ----------------------------------------
            float sacc[8][4];
#pragma unroll
            for (int i = 0; i < 8; i++)
#pragma unroll
                for (int j = 0; j < 4; j++) sacc[i][j] = 0.f;

#pragma unroll
            for (int ks = 0; ks < 8; ks++) {
                uint32_t qh[4], ql[4];
                uint32_t qaddr = sbase + (uint32_t)(qa_off + ks * 16) * 2;
                ldsm4(qh, qaddr);
                ldsm4(ql, qaddr + QSP);
#pragma unroll
                for (int np = 0; np < 4; np++) {
                    uint32_t kh[4], kl[4];
                    uint32_t kaddr = kb
                        + (uint32_t)((np * 16 + kb_row) * APAD + ks * 16 + kb_colh) * 2;
                    ldsm4(kh, kaddr);
                    ldsm4(kl, kaddr + KVSP);
#pragma unroll
                    for (int h2 = 0; h2 < 2; h2++) {
                        int nt = np * 2 + h2;
                        mma16816(sacc[nt], qh, kh[h2 * 2], kh[h2 * 2 + 1]);
                        mma16816(sacc[nt], qh, kl[h2 * 2], kl[h2 * 2 + 1]);
                        mma16816(sacc[nt], ql, kh[h2 * 2], kh[h2 * 2 + 1]);
                    }
                }
            }

            // ---- scale + mask + online softmax -----------------------------
            const bool domask = (t >= 2 * qb);
            float mx0 = -1e30f, mx1 = -1e30f;
#pragma unroll
            for (int nt = 0; nt < 8; nt++) {
                float s0 = sacc[nt][0] * scale;
                float s1 = sacc[nt][1] * scale;
                float s2 = sacc[nt][2] * scale;
                float s3 = sacc[nt][3] * scale;
                if (domask) {
                    int gc = k0 + nt * 8 + 2 * (lane & 3);
                    if (gc > grow0)     s0 = -1e30f;
                    if (gc + 1 > grow0) s1 = -1e30f;
                    if (gc > grow1)     s2 = -1e30f;
                    if (gc + 1 > grow1) s3 = -1e30f;
                }
                sacc[nt][0] = s0; sacc[nt][1] = s1;
                sacc[nt][2] = s2; sacc[nt][3] = s3;
                mx0 = fmaxf(mx0, fmaxf(s0, s1));
                mx1 = fmaxf(mx1, fmaxf(s2, s3));
            }
            mx0 = fmaxf(mx0, __shfl_xor_sync(0xffffffffu, mx0, 1));
            mx0 = fmaxf(mx0, __shfl_xor_sync(0xffffffffu, mx0, 2));
            mx1 = fmaxf(mx1, __shfl_xor_sync(0xffffffffu, mx1, 1));
            mx1 = fmaxf(mx1, __shfl_xor_sync(0xffffffffu, mx1, 2));
            float mn0 = fmaxf(m0, mx0), mn1 = fmaxf(m1, mx1);
            float c0 = __expf(m0 - mn0), c1 = __expf(m1 - mn1);
            m0 = mn0; m1 = mn1;
            l0 *= c0; l1 *= c1;
#pragma unroll
            for (int nt = 0; nt < 16; nt++) {
                oacc[nt][0] *= c0; oacc[nt][1] *= c0;
                oacc[nt][2] *= c1; oacc[nt][3] *= c1;
            }
#pragma unroll
            for (int nt = 0; nt < 8; nt++) {
                float p0 = __expf(sacc[nt][0] - m0);
                float p1 = __expf(sacc[nt][1] - m0);
                float p2 = __expf(sacc[nt][2] - m1);
                float p3 = __expf(sacc[nt][3] - m1);
                sacc[nt][0] = p0; sacc[nt][1] = p1;
                sacc[nt][2] = p2; sacc[nt][3] = p3;
                l0 += p0 + p1; l1 += p2 + p3;
            }

            // ---- O += P V (bf16x3) -----------------------------------------
#pragma unroll
            for (int kc = 0; kc < 4; kc++) {
                uint32_t ph[4], pl[4];
#pragma unroll
                for (int half = 0; half < 2; half++) {
                    const float* pp = sacc[2 * kc + half];
                    __nv_bfloat162 h01 = __floats2bfloat162_rn(pp[0], pp[1]);
                    __nv_bfloat162 h23 = __floats2bfloat162_rn(pp[2], pp[3]);
                    ph[half * 2 + 0] = *(uint32_t*)&h01;
                    ph[half * 2 + 1] = *(uint32_t*)&h23;
                    __nv_bfloat162 r01 = __floats2bfloat162_rn(
                        pp[0] - __bfloat162float(h01.x),
                        pp[1] - __bfloat162float(h01.y));
                    __nv_bfloat162 r23 = __floats2bfloat162_rn(
                        pp[2] - __bfloat162float(h23.x),
                        pp[3] - __bfloat162float(h23.y));
                    pl[half * 2 + 0] = *(uint32_t*)&r01;
                    pl[half * 2 + 1] = *(uint32_t*)&r23;
                }
                // fix ordering: a0,a1 from tile 2kc; a2,a3 from tile 2kc+1
                uint32_t pha[4] = { ph[0], ph[1], ph[2], ph[3] };
                uint32_t pla[4] = { pl[0], pl[1], pl[2], pl[3] };
#pragma unroll
                for (int np = 0; np < 8; np++) {
                    uint32_t vh[4], vl[4];
                    uint32_t vaddr = kb + 2 * KVSP
                        + (uint32_t)((kc * 16 + v_key) * APAD + np * 16 + v_hd) * 2;
                    ldsm4t(vh, vaddr);
                    ldsm4t(vl, vaddr + KVSP);
                    mma16816(oacc[2 * np],     pha, vh[0], vh[1]);
                    mma16816(oacc[2 * np],     pha, vl[0], vl[1]);
                    mma16816(oacc[2 * np],     pla, vh[0], vh[1]);
                    mma16816(oacc[2 * np + 1], pha, vh[2], vh[3]);
                    mma16816(oacc[2 * np + 1], pha, vl[2], vl[3]);
                    mma16816(oacc[2 * np + 1], pla, vh[2], vh[3]);
                }
            }
        }
        __syncthreads();
        load_kv(t + 2, t & 1);
    }

    // ---- epilogue: normalize, split to bf16 hi/lo, store --------------------
    l0 += __shfl_xor_sync(0xffffffffu, l0, 1);
    l0 += __shfl_xor_sync(0xffffffffu, l0, 2);
    l1 += __shfl_xor_sync(0xffffffffu, l1, 1);
    l1 += __shfl_xor_sync(0xffffffffu, l1, 2);
    float inv0 = 1.f / l0, inv1 = 1.f / l1;

    size_t gr0 = (size_t)(bs + grow0);
    size_t gr1 = (size_t)(bs + grow1);
#pragma unroll
    for (int nt = 0; nt < 16; nt++) {
        int col = h * HD + nt * 8 + 2 * (lane & 3);
        float o0 = oacc[nt][0] * inv0, o1 = oacc[nt][1] * inv0;
        float o2 = oacc[nt][2] * inv1, o3 = oacc[nt][3] * inv1;
        __nv_bfloat162 h0 = __floats2bfloat162_rn(o0, o1);
        __nv_bfloat162 h1 = __floats2bfloat162_rn(o2, o3);
        __nv_bfloat162 e0 = __floats2bfloat162_rn(o0 - __bfloat162float(h0.x),
                                                  o1 - __bfloat162float(h0.y));
        __nv_bfloat162 e1 = __floats2bfloat162_rn(o2 - __bfloat162float(h1.x),
                                                  o3 - __bfloat162float(h1.y));
        *(__nv_bfloat162*)(g_ahi + gr0 * DIM + col) = h0;
        *(__nv_bfloat162*)(g_alo + gr0 * DIM + col) = e0;
        *(__nv_bfloat162*)(g_ahi + gr1 * DIM + col) = h1;
        *(__nv_bfloat162*)(g_alo + gr1 * DIM + col) = e1;
    }
}

// ---------------------------------------------------------------------------
extern "C" void kernel_launch(void* const* d_in, const int* in_sizes, int n_in,
                              void* d_out, int out_size)
{
    (void)in_sizes; (void)n_in; (void)out_size;
    const float* x  = (const float*)d_in[0];
    const float* wq = (const float*)d_in[1];
    const float* wk = (const float*)d_in[2];
    const float* wv = (const float*)d_in[3];
    const float* wo = (const float*)d_in[4];
    const float* fc = (const float*)d_in[5];
    const float* fs = (const float*)d_in[6];
    float* out = (float*)d_out;

    float *q, *k, *v;
    cudaGetSymbolAddress((void**)&q, g_q);
    cudaGetSymbolAddress((void**)&k, g_k);
    cudaGetSymbolAddress((void**)&v, g_v);

    __nv_bfloat16 *xhi, *xlo, *wqhi, *wqlo, *wkhi, *wklo, *wvhi, *wvlo,
                  *wohi, *wolo, *ahi, *alo, *vhi, *vlo;
    cudaGetSymbolAddress((void**)&xhi,  g_xhi);
    cudaGetSymbolAddress((void**)&xlo,  g_xlo);
    cudaGetSymbolAddress((void**)&wqhi, g_wqhi);
    cudaGetSymbolAddress((void**)&wqlo, g_wqlo);
    cudaGetSymbolAddress((void**)&wkhi, g_wkhi);
    cudaGetSymbolAddress((void**)&wklo, g_wklo);
    cudaGetSymbolAddress((void**)&wvhi, g_wvhi);
    cudaGetSymbolAddress((void**)&wvlo, g_wvlo);
    cudaGetSymbolAddress((void**)&wohi, g_wohi);
    cudaGetSymbolAddress((void**)&wolo, g_wolo);
    cudaGetSymbolAddress((void**)&ahi,  g_ahi);
    cudaGetSymbolAddress((void**)&alo,  g_alo);
    cudaGetSymbolAddress((void**)&vhi,  g_vhi);
    cudaGetSymbolAddress((void**)&vlo,  g_vlo);

    cudaFuncSetAttribute(gemm_mma,
                         cudaFuncAttributeMaxDynamicSharedMemorySize, GEMM_SMEM);
    cudaFuncSetAttribute(attn_mma,
                         cudaFuncAttributeMaxDynamicSharedMemorySize, ATTN_SMEM);

    const int NBIG = MROWS * KDIM;
    const int NKV  = KVDIM * KDIM;
    split_kernel<<<(NBIG + 255) / 256, 256>>>(x,  xhi,  xlo,  NBIG);
    split_kernel<<<(NBIG + 255) / 256, 256>>>(wq, wqhi, wqlo, NBIG);
    split_kernel<<<(NKV  + 255) / 256, 256>>>(wk, wkhi, wklo, NKV);
    split_kernel<<<(NKV  + 255) / 256, 256>>>(wv, wvhi, wvlo, NKV);
    split_kernel<<<(NBIG + 255) / 256, 256>>>(wo, wohi, wolo, NBIG);

    // QKV projections
    gemm_mma<<<dim3(DIM / BN,   MROWS / BM), 256, GEMM_SMEM>>>(
        xhi, xlo, wqhi, wqlo, q, DIM);
    gemm_mma<<<dim3(KVDIM / BN, MROWS / BM), 256, GEMM_SMEM>>>(
        xhi, xlo, wkhi, wklo, k, KVDIM);
    gemm_mma<<<dim3(KVDIM / BN, MROWS / BM), 256, GEMM_SMEM>>>(
        xhi, xlo, wvhi, wvlo, v, KVDIM);

    // RoPE + split Q,K ; split V
    const int total_pairs = MROWS * (DIM / 2) + MROWS * (KVDIM / 2);
    rope_split_kernel<<<(total_pairs + 255) / 256, 256>>>(fc, fs);
    const int NV = MROWS * KVDIM;
    split_kernel<<<(NV + 255) / 256, 256>>>(v, vhi, vlo, NV);

    // Tensor-core flash attention -> writes g_ahi/g_alo
    attn_mma<<<dim3(S_LEN / 128, NH, BATCH), 256, ATTN_SMEM>>>();

    // O projection
    gemm_mma<<<dim3(DIM / BN, MROWS / BM), 256, GEMM_SMEM>>>(
        ahi, alo, wohi, wolo, out, DIM);
}